// round 14
// baseline (speedup 1.0000x reference)
#include <cuda_runtime.h>
#include <cuda_fp16.h>
#include <math.h>
#include <stdint.h>

#define NLAYER 4
#define NHEAD  16
#define DIM    1024
#define HDIM   64
#define VOCAB  32000
#define BATCH  2
#define SEQ    2048
#define MTOK   (BATCH*SEQ)   // 4096

// ---------------- scratch (static __device__, allocation-free) ----------------
__device__ float  g_x  [MTOK * DIM];           // residual stream (fp32)
__device__ __half g_h  [MTOK * DIM];           // ln output (fp16)
__device__ __half g_qkv[MTOK * 3 * DIM];       // qkv (fp16)
__device__ __half g_y  [MTOK * DIM];           // attention out (fp16)
__device__ __half g_ffh[MTOK * 4 * DIM];       // ffn hidden (fp16)
// fp16 weight copies
__device__ __half g_wqkv[NLAYER * 3 * DIM * DIM];
__device__ __half g_wproj[NLAYER * DIM * DIM];
__device__ __half g_wf1 [NLAYER * 4 * DIM * DIM];
__device__ __half g_wf2 [NLAYER * DIM * 4 * DIM];
__device__ __half g_wemb[VOCAB * DIM];

// ---------------- fp32 -> fp16 conversion --------------------------------------
__global__ void cvth_kernel(const float* __restrict__ in, __half* __restrict__ out, int n4) {
    int stride = gridDim.x * blockDim.x;
    for (int i = blockIdx.x * blockDim.x + threadIdx.x; i < n4; i += stride) {
        float4 v = ((const float4*)in)[i];
        __half2 h0 = __floats2half2_rn(v.x, v.y);
        __half2 h1 = __floats2half2_rn(v.z, v.w);
        ((__half2*)out)[2*i]   = h0;
        ((__half2*)out)[2*i+1] = h1;
    }
}

// ---------------- embedding ----------------------------------------------------
__global__ void embed_kernel(const int* __restrict__ ids,
                             const float* __restrict__ ctx,
                             const float* __restrict__ tok,
                             const float* __restrict__ pos,
                             float* __restrict__ x) {
    int m = blockIdx.x;
    int t = m % SEQ, b = m / SEQ;
    int id = ids[m];
    int i = threadIdx.x;
    float4 a = ((const float4*)(tok + (size_t)id * DIM))[i];
    float4 p = ((const float4*)(pos + (size_t)t  * DIM))[i];
    float4 c = ((const float4*)(ctx + (size_t)b  * DIM))[i];
    a.x += p.x + c.x; a.y += p.y + c.y; a.z += p.z + c.z; a.w += p.w + c.w;
    ((float4*)(x + (size_t)m * DIM))[i] = a;
}

// ---------------- layernorm (fp32 in, fp16 out — feeds GEMMs only) -------------
__global__ void ln_kernel(const float* __restrict__ x,
                          const float* __restrict__ gw,
                          const float* __restrict__ gb,
                          __half* __restrict__ out) {
    int m = blockIdx.x;
    int i = threadIdx.x;
    float4 v = ((const float4*)(x + (size_t)m * DIM))[i];
    float s  = v.x + v.y + v.z + v.w;
    float sq = v.x*v.x + v.y*v.y + v.z*v.z + v.w*v.w;
    #pragma unroll
    for (int o = 16; o > 0; o >>= 1) {
        s  += __shfl_down_sync(0xffffffffu, s,  o);
        sq += __shfl_down_sync(0xffffffffu, sq, o);
    }
    __shared__ float sh_s[8], sh_q[8];
    int w = i >> 5, lane = i & 31;
    if (lane == 0) { sh_s[w] = s; sh_q[w] = sq; }
    __syncthreads();
    if (i == 0) {
        float ts = 0.f, tq = 0.f;
        #pragma unroll
        for (int k = 0; k < 8; k++) { ts += sh_s[k]; tq += sh_q[k]; }
        float mean = ts * (1.0f / DIM);
        float var  = tq * (1.0f / DIM) - mean * mean;
        sh_s[0] = mean;
        sh_q[0] = rsqrtf(var + 1e-5f);
    }
    __syncthreads();
    float mean = sh_s[0], rstd = sh_q[0];
    float4 wv = ((const float4*)gw)[i];
    float4 bv = ((const float4*)gb)[i];
    float r0 = (v.x - mean) * rstd * wv.x + bv.x;
    float r1 = (v.y - mean) * rstd * wv.y + bv.y;
    float r2 = (v.z - mean) * rstd * wv.z + bv.z;
    float r3 = (v.w - mean) * rstd * wv.w + bv.w;
    __half2* op = (__half2*)(out + (size_t)m * DIM);
    op[2*i]   = __floats2half2_rn(r0, r1);
    op[2*i+1] = __floats2half2_rn(r2, r3);
}

// ================= fp16 tensor-core GEMM ========================================
// C[M,N] = A[M,K] @ W[N,K]^T ; A,W fp16, accum fp32.
// modes: 0 +bias -> half C ; 1 +bias+res -> float C ; 2 gelu(+bias) -> half C ; 3 plain -> float C
__device__ __forceinline__ float gelu_exact(float v) {
    return 0.5f * v * (1.0f + erff(v * 0.70710678118654752f));
}

#define CP_ASYNC16(dst, src) \
    asm volatile("cp.async.ca.shared.global [%0], [%1], 16;\n" :: "r"(dst), "l"(src))
#define CP_COMMIT() asm volatile("cp.async.commit_group;\n" ::)
#define CP_WAIT1()  asm volatile("cp.async.wait_group 1;\n" ::)
#define CP_WAIT0()  asm volatile("cp.async.wait_group 0;\n" ::)

#define LDMATRIX_X4(r0, r1, r2, r3, addr) \
    asm volatile("ldmatrix.sync.aligned.m8n8.x4.shared.b16 {%0,%1,%2,%3}, [%4];" \
                 : "=r"(r0), "=r"(r1), "=r"(r2), "=r"(r3) : "r"(addr))

#define MMA_F16(c0, c1, c2, c3, a0, a1, a2, a3, b0, b1) \
    asm volatile("mma.sync.aligned.m16n8k16.row.col.f32.f16.f16.f32 " \
                 "{%0,%1,%2,%3}, {%4,%5,%6,%7}, {%8,%9}, {%0,%1,%2,%3};" \
                 : "+f"(c0), "+f"(c1), "+f"(c2), "+f"(c3) \
                 : "r"(a0), "r"(a1), "r"(a2), "r"(a3), "r"(b0), "r"(b1))

// CTA tile 128M x 128N x 64K ; 256 threads (8 warps, 4M x 2N, warp tile 32x64)
#define TILE_BYTES 16384          // 128 rows * 64 halves * 2B = 128B/row
#define NSTAGE 3
#define GEMM_SMEM (2 * NSTAGE * TILE_BYTES)   // 96 KB

__global__ __launch_bounds__(256, 2)
void hgemm_kernel(const __half* __restrict__ A, const __half* __restrict__ W,
                  const float* __restrict__ bias, const float* __restrict__ res,
                  void* __restrict__ Cv, int M, int N, int K, int mode) {
    extern __shared__ char smem[];
    const int tid  = threadIdx.x;
    const int wid  = tid >> 5, lane = tid & 31;
    const int m0   = blockIdx.x * 128;   // M fastest -> consecutive CTAs share W strip
    const int n0   = blockIdx.y * 128;
    const int warp_m = (wid & 3) * 32;
    const int warp_n = (wid >> 2) * 64;

    uint32_t smem_u = (uint32_t)__cvta_generic_to_shared(smem);
    const uint32_t sA = smem_u;
    const uint32_t sB = smem_u + NSTAGE * TILE_BYTES;

    float acc[2][8][4];
    #pragma unroll
    for (int i = 0; i < 2; i++)
        #pragma unroll
        for (int j = 0; j < 8; j++)
            #pragma unroll
            for (int q = 0; q < 4; q++) acc[i][j][q] = 0.f;

    const __half* Agb = A + (size_t)m0 * K;
    const __half* Wgb = W + (size_t)n0 * K;

    auto prefetch = [&](int kt, int buf) {
        #pragma unroll
        for (int i = 0; i < 4; i++) {
            int g = tid + i * 256;          // 0..1023
            int row = g >> 3, ch = g & 7;   // 128 rows x 8 chunks of 16B
            uint32_t off = (uint32_t)(row * 128 + ((ch ^ (row & 7)) << 4));
            CP_ASYNC16(sA + buf * TILE_BYTES + off, Agb + (size_t)row * K + kt * 64 + ch * 8);
            CP_ASYNC16(sB + buf * TILE_BYTES + off, Wgb + (size_t)row * K + kt * 64 + ch * 8);
        }
        CP_COMMIT();
    };

    const int T = K / 64;
    prefetch(0, 0);
    prefetch(1, 1);

    for (int t = 0; t < T; t++) {
        const int s = t % NSTAGE;
        if (t + 1 < T) { CP_WAIT1(); } else { CP_WAIT0(); }
        __syncthreads();

        if (t + 2 < T) prefetch(t + 2, (t + 2) % NSTAGE);

        const uint32_t baseA = sA + s * TILE_BYTES;
        const uint32_t baseB = sB + s * TILE_BYTES;

        #pragma unroll
        for (int k16 = 0; k16 < 4; k16++) {
            // A fragments: canonical x4 (row = base + lane%16, chunk-half = lane/16)
            uint32_t af[2][4];
            #pragma unroll
            for (int mt = 0; mt < 2; mt++) {
                int row = warp_m + mt * 16 + (lane & 15);
                int ch  = k16 * 2 + (lane >> 4);
                uint32_t addr = baseA + row * 128 + ((ch ^ (row & 7)) << 4);
                LDMATRIX_X4(af[mt][0], af[mt][1], af[mt][2], af[mt][3], addr);
            }
            // B fragments: matrices ordered (n-lo k-lo)(n-lo k-hi)(n-hi k-lo)(n-hi k-hi)
            uint32_t bq[4][4];
            #pragma unroll
            for (int nb = 0; nb < 4; nb++) {
                int row = warp_n + nb * 16 + ((lane >> 4) << 3) + (lane & 7);
                int ch  = k16 * 2 + ((lane >> 3) & 1);
                uint32_t addr = baseB + row * 128 + ((ch ^ (row & 7)) << 4);
                LDMATRIX_X4(bq[nb][0], bq[nb][1], bq[nb][2], bq[nb][3], addr);
            }
            #pragma unroll
            for (int mt = 0; mt < 2; mt++) {
                #pragma unroll
                for (int nb = 0; nb < 4; nb++) {
                    MMA_F16(acc[mt][2*nb][0],   acc[mt][2*nb][1],   acc[mt][2*nb][2],   acc[mt][2*nb][3],
                            af[mt][0], af[mt][1], af[mt][2], af[mt][3], bq[nb][0], bq[nb][1]);
                    MMA_F16(acc[mt][2*nb+1][0], acc[mt][2*nb+1][1], acc[mt][2*nb+1][2], acc[mt][2*nb+1][3],
                            af[mt][0], af[mt][1], af[mt][2], af[mt][3], bq[nb][2], bq[nb][3]);
                }
            }
        }
    }

    // ---------------- epilogue ----------------
    #pragma unroll
    for (int mt = 0; mt < 2; mt++) {
        int rr = m0 + warp_m + mt * 16 + (lane >> 2);
        #pragma unroll
        for (int nt = 0; nt < 8; nt++) {
            int cc = n0 + warp_n + nt * 8 + (lane & 3) * 2;
            float b0 = 0.f, b1 = 0.f;
            if (mode != 3) { b0 = bias[cc]; b1 = bias[cc + 1]; }
            float v0 = acc[mt][nt][0] + b0, v1 = acc[mt][nt][1] + b1;
            float v2 = acc[mt][nt][2] + b0, v3 = acc[mt][nt][3] + b1;
            size_t o0 = (size_t)rr * N + cc;
            size_t o1 = (size_t)(rr + 8) * N + cc;
            if (mode == 1) {          // + residual, fp32 out
                float* C = (float*)Cv;
                float2 r0 = *(const float2*)(res + o0);
                float2 r1 = *(const float2*)(res + o1);
                *(float2*)(C + o0) = make_float2(v0 + r0.x, v1 + r0.y);
                *(float2*)(C + o1) = make_float2(v2 + r1.x, v3 + r1.y);
            } else if (mode == 3) {   // plain fp32 out (logits)
                float* C = (float*)Cv;
                *(float2*)(C + o0) = make_float2(v0, v1);
                *(float2*)(C + o1) = make_float2(v2, v3);
            } else {                  // fp16 out
                if (mode == 2) {
                    v0 = gelu_exact(v0); v1 = gelu_exact(v1);
                    v2 = gelu_exact(v2); v3 = gelu_exact(v3);
                }
                __half* C = (__half*)Cv;
                *(__half2*)(C + o0) = __floats2half2_rn(v0, v1);
                *(__half2*)(C + o1) = __floats2half2_rn(v2, v3);
            }
        }
    }
}

// ---------------- flash attention (fp16 qkv in, fp16 y out, fp32 math) ---------
#define QTILE 128
#define KTILE 64

__global__ __launch_bounds__(128)
void attn_kernel(const __half* __restrict__ qkv, __half* __restrict__ y) {
    __shared__ float Ks[KTILE][HDIM + 4];
    __shared__ float Vs[KTILE][HDIM + 4];

    int bh = blockIdx.y;
    int b = bh / NHEAD, h = bh % NHEAD;
    int q0 = blockIdx.x * QTILE;
    int tid = threadIdx.x;
    int qi = q0 + tid;

    const __half* qp = qkv + ((size_t)(b * SEQ + qi)) * (3 * DIM) + h * HDIM;
    float q[HDIM], o[HDIM];
    #pragma unroll
    for (int d = 0; d < HDIM; d++) { q[d] = __half2float(qp[d]) * 0.125f; o[d] = 0.f; }
    float mval = -1e30f, l = 0.f;

    int nkt = q0 / KTILE + 2;
    int c  = tid & 63;
    int r0 = tid >> 6;

    for (int kt = 0; kt < nkt; kt++) {
        int k0 = kt * KTILE;
        for (int r = r0; r < KTILE; r += 2) {
            size_t base = ((size_t)(b * SEQ + k0 + r)) * (3 * DIM) + h * HDIM + c;
            Ks[r][c] = __half2float(qkv[base + DIM]);
            Vs[r][c] = __half2float(qkv[base + 2 * DIM]);
        }
        __syncthreads();

        #pragma unroll
        for (int jc = 0; jc < KTILE; jc += 32) {
            float s[32];
            #pragma unroll
            for (int j = 0; j < 32; j++) {
                float a = 0.f;
                const float4* kr = (const float4*)Ks[jc + j];
                #pragma unroll
                for (int d4 = 0; d4 < HDIM / 4; d4++) {
                    float4 kk = kr[d4];
                    a = fmaf(q[d4*4+0], kk.x, a);
                    a = fmaf(q[d4*4+1], kk.y, a);
                    a = fmaf(q[d4*4+2], kk.z, a);
                    a = fmaf(q[d4*4+3], kk.w, a);
                }
                s[j] = ((k0 + jc + j) <= qi) ? a : -1e30f;
            }
            float tmax = s[0];
            #pragma unroll
            for (int j = 1; j < 32; j++) tmax = fmaxf(tmax, s[j]);
            if (tmax > mval) {
                float sc = __expf(mval - tmax);
                l *= sc;
                #pragma unroll
                for (int d = 0; d < HDIM; d++) o[d] *= sc;
                mval = tmax;
            }
            #pragma unroll
            for (int j = 0; j < 32; j++) {
                float p = __expf(s[j] - mval);
                l += p;
                const float4* vr = (const float4*)Vs[jc + j];
                #pragma unroll
                for (int d4 = 0; d4 < HDIM / 4; d4++) {
                    float4 vvv = vr[d4];
                    o[d4*4+0] = fmaf(p, vvv.x, o[d4*4+0]);
                    o[d4*4+1] = fmaf(p, vvv.y, o[d4*4+1]);
                    o[d4*4+2] = fmaf(p, vvv.z, o[d4*4+2]);
                    o[d4*4+3] = fmaf(p, vvv.w, o[d4*4+3]);
                }
            }
        }
        __syncthreads();
    }

    float inv = 1.f / l;
    __half2* yp = (__half2*)(y + ((size_t)(b * SEQ + qi)) * DIM + h * HDIM);
    #pragma unroll
    for (int d = 0; d < HDIM / 2; d++)
        yp[d] = __floats2half2_rn(o[2*d] * inv, o[2*d+1] * inv);
}

// ---------------- host orchestration ------------------------------------------
static inline void launch_gemm(const __half* A, const __half* W, const float* bias,
                               const float* res, void* C, int M, int N, int K, int mode) {
    dim3 grid(M / 128, N / 128);   // x = M tiles fast -> W-strip L2 reuse
    hgemm_kernel<<<grid, 256, GEMM_SMEM>>>(A, W, bias, res, C, M, N, K, mode);
}

extern "C" void kernel_launch(void* const* d_in, const int* in_sizes, int n_in,
                              void* d_out, int out_size) {
    const int*   token_ids = (const int*)  d_in[0];
    const float* ctx       = (const float*)d_in[1];
    const float* tok_emb   = (const float*)d_in[2];
    const float* pos_emb   = (const float*)d_in[3];
    const float* qkv_w     = (const float*)d_in[4];
    const float* qkv_b     = (const float*)d_in[5];
    const float* proj_w    = (const float*)d_in[6];
    const float* proj_b    = (const float*)d_in[7];
    const float* ln1_w     = (const float*)d_in[8];
    const float* ln1_b     = (const float*)d_in[9];
    const float* ln2_w     = (const float*)d_in[10];
    const float* ln2_b     = (const float*)d_in[11];
    const float* f1_w      = (const float*)d_in[12];
    const float* f1_b      = (const float*)d_in[13];
    const float* f2_w      = (const float*)d_in[14];
    const float* f2_b      = (const float*)d_in[15];
    const float* lnf_w     = (const float*)d_in[16];
    const float* lnf_b     = (const float*)d_in[17];
    float* logits = (float*)d_out;

    cudaFuncSetAttribute(hgemm_kernel, cudaFuncAttributeMaxDynamicSharedMemorySize, GEMM_SMEM);

    float  *x;
    __half *h, *qkv, *y, *ffh, *wqkv, *wproj, *wf1, *wf2, *wemb;
    cudaGetSymbolAddress((void**)&x,    g_x);
    cudaGetSymbolAddress((void**)&h,    g_h);
    cudaGetSymbolAddress((void**)&qkv,  g_qkv);
    cudaGetSymbolAddress((void**)&y,    g_y);
    cudaGetSymbolAddress((void**)&ffh,  g_ffh);
    cudaGetSymbolAddress((void**)&wqkv, g_wqkv);
    cudaGetSymbolAddress((void**)&wproj,g_wproj);
    cudaGetSymbolAddress((void**)&wf1,  g_wf1);
    cudaGetSymbolAddress((void**)&wf2,  g_wf2);
    cudaGetSymbolAddress((void**)&wemb, g_wemb);

    // fp16 weight conversion once per launch
    cvth_kernel<<<2048, 256>>>(qkv_w,   wqkv,  NLAYER * 3 * DIM * DIM / 4);
    cvth_kernel<<<1024, 256>>>(proj_w,  wproj, NLAYER * DIM * DIM / 4);
    cvth_kernel<<<2048, 256>>>(f1_w,    wf1,   NLAYER * 4 * DIM * DIM / 4);
    cvth_kernel<<<2048, 256>>>(f2_w,    wf2,   NLAYER * DIM * 4 * DIM / 4);
    cvth_kernel<<<4096, 256>>>(tok_emb, wemb,  VOCAB * DIM / 4);

    embed_kernel<<<MTOK, 256>>>(token_ids, ctx, tok_emb, pos_emb, x);

    for (int l = 0; l < NLAYER; l++) {
        ln_kernel<<<MTOK, 256>>>(x, ln1_w + l * DIM, ln1_b + l * DIM, h);
        launch_gemm(h, wqkv + (size_t)l * 3 * DIM * DIM, qkv_b + (size_t)l * 3 * DIM,
                    nullptr, qkv, MTOK, 3 * DIM, DIM, 0);
        attn_kernel<<<dim3(SEQ / QTILE, BATCH * NHEAD), 128>>>(qkv, y);
        launch_gemm(y, wproj + (size_t)l * DIM * DIM, proj_b + (size_t)l * DIM,
                    x, x, MTOK, DIM, DIM, 1);
        ln_kernel<<<MTOK, 256>>>(x, ln2_w + l * DIM, ln2_b + l * DIM, h);
        launch_gemm(h, wf1 + (size_t)l * 4 * DIM * DIM, f1_b + (size_t)l * 4 * DIM,
                    nullptr, ffh, MTOK, 4 * DIM, DIM, 2);
        launch_gemm(ffh, wf2 + (size_t)l * DIM * 4 * DIM, f2_b + (size_t)l * DIM,
                    x, x, MTOK, DIM, 4 * DIM, 1);
    }

    ln_kernel<<<MTOK, 256>>>(x, lnf_w, lnf_b, h);
    launch_gemm(h, wemb, nullptr, nullptr, logits, MTOK, VOCAB, DIM, 3);
}

// round 15
// speedup vs baseline: 1.0064x; 1.0064x over previous
#include <cuda_runtime.h>
#include <cuda_fp16.h>
#include <math.h>
#include <stdint.h>

#define NLAYER 4
#define NHEAD  16
#define DIM    1024
#define HDIM   64
#define VOCAB  32000
#define BATCH  2
#define SEQ    2048
#define MTOK   (BATCH*SEQ)   // 4096

// ---------------- scratch (static __device__, allocation-free) ----------------
__device__ float  g_x  [MTOK * DIM];           // residual stream (fp32)
__device__ __half g_h  [MTOK * DIM];           // ln output (fp16)
__device__ __half g_qkv[MTOK * 3 * DIM];       // qkv (fp16)
__device__ __half g_y  [MTOK * DIM];           // attention out (fp16)
__device__ __half g_ffh[MTOK * 4 * DIM];       // ffn hidden (fp16)
// fp16 weight copies
__device__ __half g_wqkv[NLAYER * 3 * DIM * DIM];
__device__ __half g_wproj[NLAYER * DIM * DIM];
__device__ __half g_wf1 [NLAYER * 4 * DIM * DIM];
__device__ __half g_wf2 [NLAYER * DIM * 4 * DIM];
__device__ __half g_wemb[VOCAB * DIM];

// ---------------- fp32 -> fp16 conversion --------------------------------------
__global__ void cvth_kernel(const float* __restrict__ in, __half* __restrict__ out, int n4) {
    int stride = gridDim.x * blockDim.x;
    for (int i = blockIdx.x * blockDim.x + threadIdx.x; i < n4; i += stride) {
        float4 v = ((const float4*)in)[i];
        __half2 h0 = __floats2half2_rn(v.x, v.y);
        __half2 h1 = __floats2half2_rn(v.z, v.w);
        ((__half2*)out)[2*i]   = h0;
        ((__half2*)out)[2*i+1] = h1;
    }
}

// ---------------- embedding ----------------------------------------------------
__global__ void embed_kernel(const int* __restrict__ ids,
                             const float* __restrict__ ctx,
                             const float* __restrict__ tok,
                             const float* __restrict__ pos,
                             float* __restrict__ x) {
    int m = blockIdx.x;
    int t = m % SEQ, b = m / SEQ;
    int id = ids[m];
    int i = threadIdx.x;
    float4 a = ((const float4*)(tok + (size_t)id * DIM))[i];
    float4 p = ((const float4*)(pos + (size_t)t  * DIM))[i];
    float4 c = ((const float4*)(ctx + (size_t)b  * DIM))[i];
    a.x += p.x + c.x; a.y += p.y + c.y; a.z += p.z + c.z; a.w += p.w + c.w;
    ((float4*)(x + (size_t)m * DIM))[i] = a;
}

// ---------------- layernorm (fp32 in, fp16 out — feeds GEMMs only) -------------
__global__ void ln_kernel(const float* __restrict__ x,
                          const float* __restrict__ gw,
                          const float* __restrict__ gb,
                          __half* __restrict__ out) {
    int m = blockIdx.x;
    int i = threadIdx.x;
    float4 v = ((const float4*)(x + (size_t)m * DIM))[i];
    float s  = v.x + v.y + v.z + v.w;
    float sq = v.x*v.x + v.y*v.y + v.z*v.z + v.w*v.w;
    #pragma unroll
    for (int o = 16; o > 0; o >>= 1) {
        s  += __shfl_down_sync(0xffffffffu, s,  o);
        sq += __shfl_down_sync(0xffffffffu, sq, o);
    }
    __shared__ float sh_s[8], sh_q[8];
    int w = i >> 5, lane = i & 31;
    if (lane == 0) { sh_s[w] = s; sh_q[w] = sq; }
    __syncthreads();
    if (i == 0) {
        float ts = 0.f, tq = 0.f;
        #pragma unroll
        for (int k = 0; k < 8; k++) { ts += sh_s[k]; tq += sh_q[k]; }
        float mean = ts * (1.0f / DIM);
        float var  = tq * (1.0f / DIM) - mean * mean;
        sh_s[0] = mean;
        sh_q[0] = rsqrtf(var + 1e-5f);
    }
    __syncthreads();
    float mean = sh_s[0], rstd = sh_q[0];
    float4 wv = ((const float4*)gw)[i];
    float4 bv = ((const float4*)gb)[i];
    float r0 = (v.x - mean) * rstd * wv.x + bv.x;
    float r1 = (v.y - mean) * rstd * wv.y + bv.y;
    float r2 = (v.z - mean) * rstd * wv.z + bv.z;
    float r3 = (v.w - mean) * rstd * wv.w + bv.w;
    __half2* op = (__half2*)(out + (size_t)m * DIM);
    op[2*i]   = __floats2half2_rn(r0, r1);
    op[2*i+1] = __floats2half2_rn(r2, r3);
}

// ================= fp16 tensor-core GEMM ========================================
// C[M,N] = A[M,K] @ W[N,K]^T ; A,W fp16, accum fp32.
// modes: 0 +bias -> half C ; 1 +bias+res -> float C ; 2 gelu(+bias) -> half C ; 3 plain -> float C
__device__ __forceinline__ float gelu_exact(float v) {
    return 0.5f * v * (1.0f + erff(v * 0.70710678118654752f));
}

#define CP_ASYNC16(dst, src) \
    asm volatile("cp.async.ca.shared.global [%0], [%1], 16;\n" :: "r"(dst), "l"(src))
#define CP_COMMIT() asm volatile("cp.async.commit_group;\n" ::)
#define CP_WAIT1()  asm volatile("cp.async.wait_group 1;\n" ::)
#define CP_WAIT0()  asm volatile("cp.async.wait_group 0;\n" ::)

#define LDMATRIX_X4(r0, r1, r2, r3, addr) \
    asm volatile("ldmatrix.sync.aligned.m8n8.x4.shared.b16 {%0,%1,%2,%3}, [%4];" \
                 : "=r"(r0), "=r"(r1), "=r"(r2), "=r"(r3) : "r"(addr))

#define MMA_F16(c0, c1, c2, c3, a0, a1, a2, a3, b0, b1) \
    asm volatile("mma.sync.aligned.m16n8k16.row.col.f32.f16.f16.f32 " \
                 "{%0,%1,%2,%3}, {%4,%5,%6,%7}, {%8,%9}, {%0,%1,%2,%3};" \
                 : "+f"(c0), "+f"(c1), "+f"(c2), "+f"(c3) \
                 : "r"(a0), "r"(a1), "r"(a2), "r"(a3), "r"(b0), "r"(b1))

// CTA tile 128M x 128N x 64K ; 256 threads (8 warps, 4M x 2N, warp tile 32x64)
#define TILE_BYTES 16384          // 128 rows * 64 halves * 2B = 128B/row
#define NSTAGE 3
#define GEMM_SMEM (2 * NSTAGE * TILE_BYTES)   // 96 KB

__global__ __launch_bounds__(256, 2)
void hgemm_kernel(const __half* __restrict__ A, const __half* __restrict__ W,
                  const float* __restrict__ bias, const float* __restrict__ res,
                  void* __restrict__ Cv, int M, int N, int K, int mode) {
    extern __shared__ char smem[];
    const int tid  = threadIdx.x;
    const int wid  = tid >> 5, lane = tid & 31;
    const int m0   = blockIdx.x * 128;   // M fastest -> consecutive CTAs share W strip
    const int n0   = blockIdx.y * 128;
    const int warp_m = (wid & 3) * 32;
    const int warp_n = (wid >> 2) * 64;

    uint32_t smem_u = (uint32_t)__cvta_generic_to_shared(smem);
    const uint32_t sA = smem_u;
    const uint32_t sB = smem_u + NSTAGE * TILE_BYTES;

    float acc[2][8][4];
    #pragma unroll
    for (int i = 0; i < 2; i++)
        #pragma unroll
        for (int j = 0; j < 8; j++)
            #pragma unroll
            for (int q = 0; q < 4; q++) acc[i][j][q] = 0.f;

    const __half* Agb = A + (size_t)m0 * K;
    const __half* Wgb = W + (size_t)n0 * K;

    auto prefetch = [&](int kt, int buf) {
        #pragma unroll
        for (int i = 0; i < 4; i++) {
            int g = tid + i * 256;          // 0..1023
            int row = g >> 3, ch = g & 7;   // 128 rows x 8 chunks of 16B
            uint32_t off = (uint32_t)(row * 128 + ((ch ^ (row & 7)) << 4));
            CP_ASYNC16(sA + buf * TILE_BYTES + off, Agb + (size_t)row * K + kt * 64 + ch * 8);
            CP_ASYNC16(sB + buf * TILE_BYTES + off, Wgb + (size_t)row * K + kt * 64 + ch * 8);
        }
        CP_COMMIT();
    };

    const int T = K / 64;
    prefetch(0, 0);
    prefetch(1, 1);

    for (int t = 0; t < T; t++) {
        const int s = t % NSTAGE;
        if (t + 1 < T) { CP_WAIT1(); } else { CP_WAIT0(); }
        __syncthreads();

        if (t + 2 < T) prefetch(t + 2, (t + 2) % NSTAGE);

        const uint32_t baseA = sA + s * TILE_BYTES;
        const uint32_t baseB = sB + s * TILE_BYTES;

        #pragma unroll
        for (int k16 = 0; k16 < 4; k16++) {
            // A fragments: canonical x4 (row = base + lane%16, chunk-half = lane/16)
            uint32_t af[2][4];
            #pragma unroll
            for (int mt = 0; mt < 2; mt++) {
                int row = warp_m + mt * 16 + (lane & 15);
                int ch  = k16 * 2 + (lane >> 4);
                uint32_t addr = baseA + row * 128 + ((ch ^ (row & 7)) << 4);
                LDMATRIX_X4(af[mt][0], af[mt][1], af[mt][2], af[mt][3], addr);
            }
            // B fragments: matrices ordered (n-lo k-lo)(n-lo k-hi)(n-hi k-lo)(n-hi k-hi)
            uint32_t bq[4][4];
            #pragma unroll
            for (int nb = 0; nb < 4; nb++) {
                int row = warp_n + nb * 16 + ((lane >> 4) << 3) + (lane & 7);
                int ch  = k16 * 2 + ((lane >> 3) & 1);
                uint32_t addr = baseB + row * 128 + ((ch ^ (row & 7)) << 4);
                LDMATRIX_X4(bq[nb][0], bq[nb][1], bq[nb][2], bq[nb][3], addr);
            }
            #pragma unroll
            for (int mt = 0; mt < 2; mt++) {
                #pragma unroll
                for (int nb = 0; nb < 4; nb++) {
                    MMA_F16(acc[mt][2*nb][0],   acc[mt][2*nb][1],   acc[mt][2*nb][2],   acc[mt][2*nb][3],
                            af[mt][0], af[mt][1], af[mt][2], af[mt][3], bq[nb][0], bq[nb][1]);
                    MMA_F16(acc[mt][2*nb+1][0], acc[mt][2*nb+1][1], acc[mt][2*nb+1][2], acc[mt][2*nb+1][3],
                            af[mt][0], af[mt][1], af[mt][2], af[mt][3], bq[nb][2], bq[nb][3]);
                }
            }
        }
    }

    // ---------------- epilogue ----------------
    #pragma unroll
    for (int mt = 0; mt < 2; mt++) {
        int rr = m0 + warp_m + mt * 16 + (lane >> 2);
        #pragma unroll
        for (int nt = 0; nt < 8; nt++) {
            int cc = n0 + warp_n + nt * 8 + (lane & 3) * 2;
            float b0 = 0.f, b1 = 0.f;
            if (mode != 3) { b0 = bias[cc]; b1 = bias[cc + 1]; }
            float v0 = acc[mt][nt][0] + b0, v1 = acc[mt][nt][1] + b1;
            float v2 = acc[mt][nt][2] + b0, v3 = acc[mt][nt][3] + b1;
            size_t o0 = (size_t)rr * N + cc;
            size_t o1 = (size_t)(rr + 8) * N + cc;
            if (mode == 1) {          // + residual, fp32 out
                float* C = (float*)Cv;
                float2 r0 = *(const float2*)(res + o0);
                float2 r1 = *(const float2*)(res + o1);
                *(float2*)(C + o0) = make_float2(v0 + r0.x, v1 + r0.y);
                *(float2*)(C + o1) = make_float2(v2 + r1.x, v3 + r1.y);
            } else if (mode == 3) {   // plain fp32 out (logits)
                float* C = (float*)Cv;
                *(float2*)(C + o0) = make_float2(v0, v1);
                *(float2*)(C + o1) = make_float2(v2, v3);
            } else {                  // fp16 out
                if (mode == 2) {
                    v0 = gelu_exact(v0); v1 = gelu_exact(v1);
                    v2 = gelu_exact(v2); v3 = gelu_exact(v3);
                }
                __half* C = (__half*)Cv;
                *(__half2*)(C + o0) = __floats2half2_rn(v0, v1);
                *(__half2*)(C + o1) = __floats2half2_rn(v2, v3);
            }
        }
    }
}

// ---------------- flash attention (fp16 qkv in, fp16 y out, fp32 math) ---------
#define QTILE 128
#define KTILE 64

__global__ __launch_bounds__(128)
void attn_kernel(const __half* __restrict__ qkv, __half* __restrict__ y) {
    __shared__ float Ks[KTILE][HDIM + 4];
    __shared__ float Vs[KTILE][HDIM + 4];

    int bh = blockIdx.y;
    int b = bh / NHEAD, h = bh % NHEAD;
    int q0 = blockIdx.x * QTILE;
    int tid = threadIdx.x;
    int qi = q0 + tid;

    const __half* qp = qkv + ((size_t)(b * SEQ + qi)) * (3 * DIM) + h * HDIM;
    float q[HDIM], o[HDIM];
    #pragma unroll
    for (int d = 0; d < HDIM; d++) { q[d] = __half2float(qp[d]) * 0.125f; o[d] = 0.f; }
    float mval = -1e30f, l = 0.f;

    int nkt = q0 / KTILE + 2;
    int c  = tid & 63;
    int r0 = tid >> 6;

    for (int kt = 0; kt < nkt; kt++) {
        int k0 = kt * KTILE;
        for (int r = r0; r < KTILE; r += 2) {
            size_t base = ((size_t)(b * SEQ + k0 + r)) * (3 * DIM) + h * HDIM + c;
            Ks[r][c] = __half2float(qkv[base + DIM]);
            Vs[r][c] = __half2float(qkv[base + 2 * DIM]);
        }
        __syncthreads();

        #pragma unroll
        for (int jc = 0; jc < KTILE; jc += 32) {
            float s[32];
            #pragma unroll
            for (int j = 0; j < 32; j++) {
                float a = 0.f;
                const float4* kr = (const float4*)Ks[jc + j];
                #pragma unroll
                for (int d4 = 0; d4 < HDIM / 4; d4++) {
                    float4 kk = kr[d4];
                    a = fmaf(q[d4*4+0], kk.x, a);
                    a = fmaf(q[d4*4+1], kk.y, a);
                    a = fmaf(q[d4*4+2], kk.z, a);
                    a = fmaf(q[d4*4+3], kk.w, a);
                }
                s[j] = ((k0 + jc + j) <= qi) ? a : -1e30f;
            }
            float tmax = s[0];
            #pragma unroll
            for (int j = 1; j < 32; j++) tmax = fmaxf(tmax, s[j]);
            if (tmax > mval) {
                float sc = __expf(mval - tmax);
                l *= sc;
                #pragma unroll
                for (int d = 0; d < HDIM; d++) o[d] *= sc;
                mval = tmax;
            }
            #pragma unroll
            for (int j = 0; j < 32; j++) {
                float p = __expf(s[j] - mval);
                l += p;
                const float4* vr = (const float4*)Vs[jc + j];
                #pragma unroll
                for (int d4 = 0; d4 < HDIM / 4; d4++) {
                    float4 vvv = vr[d4];
                    o[d4*4+0] = fmaf(p, vvv.x, o[d4*4+0]);
                    o[d4*4+1] = fmaf(p, vvv.y, o[d4*4+1]);
                    o[d4*4+2] = fmaf(p, vvv.z, o[d4*4+2]);
                    o[d4*4+3] = fmaf(p, vvv.w, o[d4*4+3]);
                }
            }
        }
        __syncthreads();
    }

    float inv = 1.f / l;
    __half2* yp = (__half2*)(y + ((size_t)(b * SEQ + qi)) * DIM + h * HDIM);
    #pragma unroll
    for (int d = 0; d < HDIM / 2; d++)
        yp[d] = __floats2half2_rn(o[2*d] * inv, o[2*d+1] * inv);
}

// ---------------- host orchestration ------------------------------------------
static inline void launch_gemm(const __half* A, const __half* W, const float* bias,
                               const float* res, void* C, int M, int N, int K, int mode) {
    dim3 grid(M / 128, N / 128);   // x = M tiles fast -> W-strip L2 reuse
    hgemm_kernel<<<grid, 256, GEMM_SMEM>>>(A, W, bias, res, C, M, N, K, mode);
}

extern "C" void kernel_launch(void* const* d_in, const int* in_sizes, int n_in,
                              void* d_out, int out_size) {
    const int*   token_ids = (const int*)  d_in[0];
    const float* ctx       = (const float*)d_in[1];
    const float* tok_emb   = (const float*)d_in[2];
    const float* pos_emb   = (const float*)d_in[3];
    const float* qkv_w     = (const float*)d_in[4];
    const float* qkv_b     = (const float*)d_in[5];
    const float* proj_w    = (const float*)d_in[6];
    const float* proj_b    = (const float*)d_in[7];
    const float* ln1_w     = (const float*)d_in[8];
    const float* ln1_b     = (const float*)d_in[9];
    const float* ln2_w     = (const float*)d_in[10];
    const float* ln2_b     = (const float*)d_in[11];
    const float* f1_w      = (const float*)d_in[12];
    const float* f1_b      = (const float*)d_in[13];
    const float* f2_w      = (const float*)d_in[14];
    const float* f2_b      = (const float*)d_in[15];
    const float* lnf_w     = (const float*)d_in[16];
    const float* lnf_b     = (const float*)d_in[17];
    float* logits = (float*)d_out;

    cudaFuncSetAttribute(hgemm_kernel, cudaFuncAttributeMaxDynamicSharedMemorySize, GEMM_SMEM);

    float  *x;
    __half *h, *qkv, *y, *ffh, *wqkv, *wproj, *wf1, *wf2, *wemb;
    cudaGetSymbolAddress((void**)&x,    g_x);
    cudaGetSymbolAddress((void**)&h,    g_h);
    cudaGetSymbolAddress((void**)&qkv,  g_qkv);
    cudaGetSymbolAddress((void**)&y,    g_y);
    cudaGetSymbolAddress((void**)&ffh,  g_ffh);
    cudaGetSymbolAddress((void**)&wqkv, g_wqkv);
    cudaGetSymbolAddress((void**)&wproj,g_wproj);
    cudaGetSymbolAddress((void**)&wf1,  g_wf1);
    cudaGetSymbolAddress((void**)&wf2,  g_wf2);
    cudaGetSymbolAddress((void**)&wemb, g_wemb);

    // fp16 weight conversion once per launch
    cvth_kernel<<<2048, 256>>>(qkv_w,   wqkv,  NLAYER * 3 * DIM * DIM / 4);
    cvth_kernel<<<1024, 256>>>(proj_w,  wproj, NLAYER * DIM * DIM / 4);
    cvth_kernel<<<2048, 256>>>(f1_w,    wf1,   NLAYER * 4 * DIM * DIM / 4);
    cvth_kernel<<<2048, 256>>>(f2_w,    wf2,   NLAYER * DIM * 4 * DIM / 4);
    cvth_kernel<<<4096, 256>>>(tok_emb, wemb,  VOCAB * DIM / 4);

    embed_kernel<<<MTOK, 256>>>(token_ids, ctx, tok_emb, pos_emb, x);

    for (int l = 0; l < NLAYER; l++) {
        ln_kernel<<<MTOK, 256>>>(x, ln1_w + l * DIM, ln1_b + l * DIM, h);
        launch_gemm(h, wqkv + (size_t)l * 3 * DIM * DIM, qkv_b + (size_t)l * 3 * DIM,
                    nullptr, qkv, MTOK, 3 * DIM, DIM, 0);
        attn_kernel<<<dim3(SEQ / QTILE, BATCH * NHEAD), 128>>>(qkv, y);
        launch_gemm(y, wproj + (size_t)l * DIM * DIM, proj_b + (size_t)l * DIM,
                    x, x, MTOK, DIM, DIM, 1);
        ln_kernel<<<MTOK, 256>>>(x, ln2_w + l * DIM, ln2_b + l * DIM, h);
        launch_gemm(h, wf1 + (size_t)l * 4 * DIM * DIM, f1_b + (size_t)l * 4 * DIM,
                    nullptr, ffh, MTOK, 4 * DIM, DIM, 2);
        launch_gemm(ffh, wf2 + (size_t)l * DIM * 4 * DIM, f2_b + (size_t)l * DIM,
                    x, x, MTOK, DIM, 4 * DIM, 1);
    }

    ln_kernel<<<MTOK, 256>>>(x, lnf_w, lnf_b, h);
    launch_gemm(h, wemb, nullptr, nullptr, logits, MTOK, VOCAB, DIM, 3);
}